// round 17
// baseline (speedup 1.0000x reference)
#include <cuda_runtime.h>
#include <cuda_bf16.h>

typedef unsigned long long ull;
typedef unsigned u32;

#define DD 96
#define HH 320
#define WW 320
#define NVOX (DD*HH*WW)
#define CIN 64
#define COUT 64
#define EPSV 1e-5f
#define SLOPE 0.01f
#define RSLOTS 4096

__device__ int   g_grid[NVOX];          // coord -> row+1, 0 = empty
__device__ float g_stats[2 * COUT];
__device__ int   g_cnt[27];
__device__ int2  g_rule[27][RSLOTS];
__device__ ull   g_wt_hi[27][1024];     // WT[k][co][ci] bf16 hi (ull = 4 bf16)
__device__ ull   g_wt_lo[27][1024];

// Side stream + events for graph-captured fork/join.
static cudaStream_t g_side;
static cudaEvent_t  g_ev_root, g_ev_rb, g_ev_clear;
namespace {
struct StreamInit {
    StreamInit() {
        cudaStreamCreateWithFlags(&g_side, cudaStreamNonBlocking);
        cudaEventCreateWithFlags(&g_ev_root,  cudaEventDisableTiming);
        cudaEventCreateWithFlags(&g_ev_rb,    cudaEventDisableTiming);
        cudaEventCreateWithFlags(&g_ev_clear, cudaEventDisableTiming);
    }
};
static StreamInit g_stream_init;
}

// ---------------- helpers ----------------
static __device__ __forceinline__ void split2(float a, float b,
                                              u32& hi, u32& lo)
{
    u32 h;
    asm("cvt.rn.bf16x2.f32 %0, %1, %2;" : "=r"(h) : "f"(b), "f"(a));
    float ha = __uint_as_float(h << 16);
    float hb = __uint_as_float(h & 0xffff0000u);
    float ra = a - ha;
    float rb = b - hb;
    u32 l;
    asm("cvt.rn.bf16x2.f32 %0, %1, %2;" : "=r"(l) : "f"(rb), "f"(ra));
    hi = h;
    lo = l;
}
static __device__ __forceinline__ void mma16816(
    float* c, const u32* a, u32 b0, u32 b1)
{
    asm volatile(
        "mma.sync.aligned.m16n8k16.row.col.f32.bf16.bf16.f32 "
        "{%0,%1,%2,%3}, {%4,%5,%6,%7}, {%8,%9}, {%0,%1,%2,%3};"
        : "+f"(c[0]), "+f"(c[1]), "+f"(c[2]), "+f"(c[3])
        : "r"(a[0]), "r"(a[1]), "r"(a[2]), "r"(a[3]), "r"(b0), "r"(b1));
}
static __device__ __forceinline__ void ldsm4(u32* r, u32 addr)
{
    asm volatile(
        "ldmatrix.sync.aligned.m8n8.x4.shared.b16 {%0,%1,%2,%3}, [%4];"
        : "=r"(r[0]), "=r"(r[1]), "=r"(r[2]), "=r"(r[3]) : "r"(addr));
}
static __device__ __forceinline__ void red4(float* addr, float4 v) {
    asm volatile("red.global.add.v4.f32 [%0], {%1, %2, %3, %4};"
                 :: "l"(addr), "f"(v.x), "f"(v.y), "f"(v.z), "f"(v.w)
                 : "memory");
}
#define ROT(row, col) (((row) << 5) + (((col) + ((row) << 2)) & 31))
#define TSTR 68

// ---------------------------------------------------------------------------
// MMA core. SMEM 48 KB. Warp tile M32 x N32 (4 row-groups x 2 col-groups):
// per kf 4 A-LDSM + 4 B-LDSM (vs 2+8 with M16xN64) -> 20% less shared-port
// traffic. 3 correction terms fused in one sweep.
// ---------------------------------------------------------------------------
struct MmaSmem {
    u32 Ahi[128 * 32];
    u32 Alo[128 * 32];
    u32 Bhi[64 * 32];
    u32 Blo[64 * 32];
};
union GemmSmem {
    MmaSmem s;
    float   tbuf[128 * TSTR];
};

static __device__ __forceinline__ void stage_B(
    MmaSmem& s, const ull* __restrict__ wh, const ull* __restrict__ wl, int tid)
{
    #pragma unroll
    for (int t = 0; t < 4; t++) {
        int e  = tid + t * 256;
        int co = e >> 4;
        int j  = e & 15;
        ull vh = wh[e];
        ull vl = wl[e];
        s.Bhi[ROT(co, 2 * j    )] = (u32)vh;
        s.Bhi[ROT(co, 2 * j + 1)] = (u32)(vh >> 32);
        s.Blo[ROT(co, 2 * j    )] = (u32)vl;
        s.Blo[ROT(co, 2 * j + 1)] = (u32)(vl >> 32);
    }
}

// acc[af][nfp][cf][4]: af = 16-row group (2), nfp = 16-col group (2),
// cf = 8-col fragment (2), 4 floats per mma result.
static __device__ __forceinline__ void mma_passes(
    const MmaSmem& s, float acc[2][2][2][4], int mrow0, int ncol0, int lane)
{
    const u32 sAhi = (u32)__cvta_generic_to_shared(s.Ahi);
    const u32 sAlo = (u32)__cvta_generic_to_shared(s.Alo);
    const u32 sBhi = (u32)__cvta_generic_to_shared(s.Bhi);
    const u32 sBlo = (u32)__cvta_generic_to_shared(s.Blo);

    const int sub = lane >> 3;
    const int l7  = lane & 7;
    const int rArel = l7 + ((sub & 1) << 3);
    const int cqA   = (sub >> 1) << 2;
    const int rBrel = ((sub >> 1) << 3) + l7;
    const int cqB   = (sub & 1) << 2;

    #pragma unroll
    for (int kf = 0; kf < 4; kf++) {
        u32 ah[2][4], al[2][4];
        #pragma unroll
        for (int af = 0; af < 2; af++) {
            int ra = mrow0 + af * 16 + rArel;
            u32 offA = 4u * ((u32)(ra << 5)
                     + (u32)((kf * 8 + cqA + (ra << 2)) & 31));
            ldsm4(ah[af], sAhi + offA);
            ldsm4(al[af], sAlo + offA);
        }
        #pragma unroll
        for (int nfp = 0; nfp < 2; nfp++) {
            int rb = ncol0 + nfp * 16 + rBrel;
            u32 offB = 4u * ((u32)(rb << 5)
                     + (u32)((kf * 8 + cqB + (rb << 2)) & 31));
            u32 bh[4], bl[4];
            ldsm4(bh, sBhi + offB);
            ldsm4(bl, sBlo + offB);
            #pragma unroll
            for (int af = 0; af < 2; af++) {
                mma16816(acc[af][nfp][0], ah[af], bh[0], bh[1]);
                mma16816(acc[af][nfp][1], ah[af], bh[2], bh[3]);
                mma16816(acc[af][nfp][0], al[af], bh[0], bh[1]);
                mma16816(acc[af][nfp][1], al[af], bh[2], bh[3]);
                mma16816(acc[af][nfp][0], ah[af], bl[0], bl[1]);
                mma16816(acc[af][nfp][1], ah[af], bl[2], bl[3]);
            }
        }
    }
}

static __device__ __forceinline__ void stage_A_row(
    MmaSmem& s, const float* __restrict__ feat, int e, int j)
{
    int r = e >> 4;
    int q = e & 15;
    float4 v = (j >= 0) ? *(const float4*)&feat[(size_t)j * CIN + q * 4]
                        : make_float4(0.f, 0.f, 0.f, 0.f);
    u32 h0, l0, h1, l1;
    split2(v.x, v.y, h0, l0);
    split2(v.z, v.w, h1, l1);
    s.Ahi[ROT(r, 2 * q    )] = h0;
    s.Ahi[ROT(r, 2 * q + 1)] = h1;
    s.Alo[ROT(r, 2 * q    )] = l0;
    s.Alo[ROT(r, 2 * q + 1)] = l1;
}

static __device__ __forceinline__ void acc_to_tbuf(
    float* tbuf, const float acc[2][2][2][4],
    int mrow0, int ncol0, int g, int tig)
{
    #pragma unroll
    for (int af = 0; af < 2; af++) {
        int r0 = mrow0 + af * 16 + g;
        #pragma unroll
        for (int nfp = 0; nfp < 2; nfp++) {
            #pragma unroll
            for (int cf = 0; cf < 2; cf++) {
                int c = ncol0 + nfp * 16 + cf * 8 + tig * 2;
                *(float2*)&tbuf[r0 * TSTR + c] =
                    make_float2(acc[af][nfp][cf][0], acc[af][nfp][cf][1]);
                *(float2*)&tbuf[(r0 + 8) * TSTR + c] =
                    make_float2(acc[af][nfp][cf][2], acc[af][nfp][cf][3]);
            }
        }
    }
}

// ---------------------------------------------------------------------------
// scatter (side stream): grid build + stats/cnt zero.
// ---------------------------------------------------------------------------
__global__ void __launch_bounds__(256) scatter_kernel(
    const int* __restrict__ coords, int n)
{
    int i = blockIdx.x * 256 + threadIdx.x;
    if (i < 2 * COUT) g_stats[i] = 0.0f;
    if (i < 27) g_cnt[i] = 0;
    if (i >= n) return;
    int z = coords[3 * i + 0];
    int y = coords[3 * i + 1];
    int x = coords[3 * i + 2];
    g_grid[(z * HH + y) * WW + x] = i + 1;
}

// wsplit (main stream): weight split, the only center dependency.
__global__ void __launch_bounds__(256) wsplit_kernel(const float* __restrict__ wgt)
{
    int idx = blockIdx.x * 256 + threadIdx.x;   // [k][co][ci]
    if (idx >= 27 * 4096) return;
    int k  = idx >> 12;
    int e  = idx & 4095;
    int co = e >> 6;
    int ci = e & 63;
    float w = wgt[(k * 64 + ci) * 64 + co];
    __nv_bfloat16 h = __float2bfloat16(w);
    float r = w - __bfloat162float(h);
    __nv_bfloat16 l = __float2bfloat16(r);
    ((__nv_bfloat16*)g_wt_hi)[idx] = h;
    ((__nv_bfloat16*)g_wt_lo)[idx] = l;
}

__global__ void __launch_bounds__(256) rulebook_kernel(
    const int* __restrict__ coords, int n)
{
    int t = blockIdx.x * blockDim.x + threadIdx.x;
    if (t >= n * 13) return;
    int v = t / 13;
    int k = t - v * 13;

    int z = coords[3 * v + 0] + k / 9       - 1;
    int y = coords[3 * v + 1] + (k / 3) % 3 - 1;
    int x = coords[3 * v + 2] + k % 3       - 1;
    if (z < 0 || z >= DD || y < 0 || y >= HH || x < 0 || x >= WW) return;
    int val = g_grid[(z * HH + y) * WW + x];
    if (val == 0) return;
    int j = val - 1;

    int p0 = atomicAdd(&g_cnt[k], 1);
    if (p0 < RSLOTS) g_rule[k][p0] = make_int2(v, j);
    int p1 = atomicAdd(&g_cnt[26 - k], 1);
    if (p1 < RSLOTS) g_rule[26 - k][p1] = make_int2(j, v);
}

__global__ void __launch_bounds__(256) clear_kernel(
    const int* __restrict__ coords, int n)
{
    int i = blockIdx.x * 256 + threadIdx.x;
    if (i < n) {
        int z = coords[3 * i + 0];
        int y = coords[3 * i + 1];
        int x = coords[3 * i + 2];
        g_grid[(z * HH + y) * WW + x] = 0;
    }
}

// ---------------------------------------------------------------------------
// Center tap: out[128 rows] = feat @ W13 (coalesced STG.128 epilogue).
// ---------------------------------------------------------------------------
__global__ void __launch_bounds__(256) center_mma_kernel(
    const float* __restrict__ feat, float* __restrict__ out, int n)
{
    __shared__ GemmSmem u;
    const int tid   = threadIdx.x;
    const int rbase = blockIdx.x * 128;

    #pragma unroll
    for (int t = 0; t < 8; t++) {
        int e  = tid + t * 256;
        int gr = rbase + (e >> 4);
        stage_A_row(u.s, feat, e, gr < n ? gr : -1);
    }
    stage_B(u.s, g_wt_hi[13], g_wt_lo[13], tid);
    __syncthreads();

    const int lane  = tid & 31;
    const int wid   = tid >> 5;
    const int mrow0 = (wid & 3) * 32;
    const int ncol0 = (wid >> 2) * 32;

    float acc[2][2][2][4];
    #pragma unroll
    for (int a = 0; a < 2; a++)
        #pragma unroll
        for (int b = 0; b < 2; b++)
            #pragma unroll
            for (int c = 0; c < 2; c++) {
                acc[a][b][c][0] = 0.f; acc[a][b][c][1] = 0.f;
                acc[a][b][c][2] = 0.f; acc[a][b][c][3] = 0.f;
            }

    mma_passes(u.s, acc, mrow0, ncol0, lane);

    __syncthreads();
    acc_to_tbuf(u.tbuf, acc, mrow0, ncol0, lane >> 2, lane & 3);
    __syncthreads();

    #pragma unroll
    for (int t = 0; t < 8; t++) {
        int e = tid + t * 256;
        int r = e >> 4;
        int q = e & 15;
        int gr = rbase + r;
        if (gr < n)
            *(float4*)&out[(size_t)gr * COUT + q * 4] =
                *(const float4*)&u.tbuf[r * TSTR + q * 4];
    }
}

// ---------------------------------------------------------------------------
// Tap GEMM: 128 rulebook pairs of ONE tap, transposed red.v4 scatter.
// ---------------------------------------------------------------------------
__global__ void __launch_bounds__(256) tap_mma_kernel(
    const float* __restrict__ feat, float* __restrict__ out)
{
    const int ky = blockIdx.y;
    int cnt = g_cnt[ky];
    if (cnt > RSLOTS) cnt = RSLOTS;
    const int base = blockIdx.x * 128;
    if (base >= cnt) return;

    __shared__ GemmSmem u;
    __shared__ int sidx[128];
    const int tid = threadIdx.x;
    const int2* rule = g_rule[ky];

    if (tid < 128)
        sidx[tid] = (base + tid < cnt) ? rule[base + tid].x : -1;

    #pragma unroll
    for (int t = 0; t < 8; t++) {
        int e = tid + t * 256;
        int r = e >> 4;
        int j = (base + r < cnt) ? rule[base + r].y : -1;
        stage_A_row(u.s, feat, e, j);
    }
    stage_B(u.s, g_wt_hi[ky], g_wt_lo[ky], tid);
    __syncthreads();

    const int lane  = tid & 31;
    const int wid   = tid >> 5;
    const int mrow0 = (wid & 3) * 32;
    const int ncol0 = (wid >> 2) * 32;

    float acc[2][2][2][4];
    #pragma unroll
    for (int a = 0; a < 2; a++)
        #pragma unroll
        for (int b = 0; b < 2; b++)
            #pragma unroll
            for (int c = 0; c < 2; c++) {
                acc[a][b][c][0] = 0.f; acc[a][b][c][1] = 0.f;
                acc[a][b][c][2] = 0.f; acc[a][b][c][3] = 0.f;
            }

    mma_passes(u.s, acc, mrow0, ncol0, lane);

    __syncthreads();
    acc_to_tbuf(u.tbuf, acc, mrow0, ncol0, lane >> 2, lane & 3);
    __syncthreads();

    #pragma unroll
    for (int t = 0; t < 8; t++) {
        int e = tid + t * 256;
        int r = e >> 4;
        int q = e & 15;
        int i = sidx[r];
        if (i >= 0) {
            float4 v = *(const float4*)&u.tbuf[r * TSTR + q * 4];
            red4(out + (size_t)i * COUT + q * 4, v);
        }
    }
}

// ---------------- BN stats reduce (pure) ----------------
#define RED_BLOCKS 1184

__global__ void __launch_bounds__(256) reduce_kernel(
    const float* __restrict__ out, int n)
{
    const int tid = threadIdx.x;
    const int c4  = (tid & 15) << 2;
    const int rg  = tid >> 4;

    float4 sv = make_float4(0.f, 0.f, 0.f, 0.f);
    float4 qv = make_float4(0.f, 0.f, 0.f, 0.f);

    for (int row = blockIdx.x * 16 + rg; row < n; row += RED_BLOCKS * 16) {
        float4 v = *(const float4*)&out[(size_t)row * COUT + c4];
        sv.x += v.x; sv.y += v.y; sv.z += v.z; sv.w += v.w;
        qv.x += v.x * v.x; qv.y += v.y * v.y;
        qv.z += v.z * v.z; qv.w += v.w * v.w;
    }

    sv.x += __shfl_xor_sync(0xffffffffu, sv.x, 16);
    sv.y += __shfl_xor_sync(0xffffffffu, sv.y, 16);
    sv.z += __shfl_xor_sync(0xffffffffu, sv.z, 16);
    sv.w += __shfl_xor_sync(0xffffffffu, sv.w, 16);
    qv.x += __shfl_xor_sync(0xffffffffu, qv.x, 16);
    qv.y += __shfl_xor_sync(0xffffffffu, qv.y, 16);
    qv.z += __shfl_xor_sync(0xffffffffu, qv.z, 16);
    qv.w += __shfl_xor_sync(0xffffffffu, qv.w, 16);

    __shared__ float wred[2][8][COUT];
    const int w = tid >> 5;
    if ((tid & 31) < 16) {
        *(float4*)&wred[0][w][c4] = sv;
        *(float4*)&wred[1][w][c4] = qv;
    }
    __syncthreads();

    if (tid < 2 * COUT) {
        int half = tid >> 6;
        int c    = tid & 63;
        float acc = 0.f;
        #pragma unroll
        for (int ww = 0; ww < 8; ww++) acc += wred[half][ww][c];
        atomicAdd(&g_stats[tid], acc);
    }
}

// ---------------- BN + LeakyReLU (4 float4 per thread) ----------------
__global__ void __launch_bounds__(256) bn_kernel(
    float4* __restrict__ out, const float* __restrict__ gamma,
    const float* __restrict__ beta, int n4, float invN)
{
    __shared__ float ssc[COUT], sbi[COUT];
    if (threadIdx.x < COUT) {
        float mean = g_stats[threadIdx.x] * invN;
        float var  = g_stats[COUT + threadIdx.x] * invN - mean * mean;
        float sc   = gamma[threadIdx.x] * rsqrtf(var + EPSV);
        ssc[threadIdx.x] = sc;
        sbi[threadIdx.x] = beta[threadIdx.x] - mean * sc;
    }
    __syncthreads();

    const int base = blockIdx.x * 1024 + threadIdx.x;

    float4 v[4];
    #pragma unroll
    for (int k = 0; k < 4; k++) {
        int idx = base + k * 256;
        if (idx < n4) v[k] = out[idx];
    }
    #pragma unroll
    for (int k = 0; k < 4; k++) {
        int idx = base + k * 256;
        if (idx >= n4) continue;
        int c4 = (idx & 15) << 2;
        float r;
        r = v[k].x * ssc[c4 + 0] + sbi[c4 + 0]; v[k].x = (r >= 0.f) ? r : SLOPE * r;
        r = v[k].y * ssc[c4 + 1] + sbi[c4 + 1]; v[k].y = (r >= 0.f) ? r : SLOPE * r;
        r = v[k].z * ssc[c4 + 2] + sbi[c4 + 2]; v[k].z = (r >= 0.f) ? r : SLOPE * r;
        r = v[k].w * ssc[c4 + 3] + sbi[c4 + 3]; v[k].w = (r >= 0.f) ? r : SLOPE * r;
        out[idx] = v[k];
    }
}

extern "C" void kernel_launch(void* const* d_in, const int* in_sizes, int n_in,
                              void* d_out, int out_size)
{
    const float* feat   = (const float*)d_in[0];
    const int*   coords = (const int*)  d_in[1];
    const float* wgt    = (const float*)d_in[2];
    const float* gamma  = (const float*)d_in[3];
    const float* beta   = (const float*)d_in[4];
    float*       out    = (float*)d_out;

    const int n = in_sizes[0] / CIN;
    const int scatter_blocks = (n + 255) / 256;

    // main: wsplit -> center -> [wait rb] tap -> reduce -> [wait clear] bn
    // side: [wait root] scatter -> rulebook -> clear
    cudaEventRecord(g_ev_root, 0);
    cudaStreamWaitEvent(g_side, g_ev_root, 0);

    scatter_kernel<<<scatter_blocks, 256, 0, g_side>>>(coords, n);
    rulebook_kernel<<<(n * 13 + 255) / 256, 256, 0, g_side>>>(coords, n);
    cudaEventRecord(g_ev_rb, g_side);
    clear_kernel<<<scatter_blocks, 256, 0, g_side>>>(coords, n);
    cudaEventRecord(g_ev_clear, g_side);

    wsplit_kernel<<<(27 * 4096 + 255) / 256, 256>>>(wgt);
    center_mma_kernel<<<(n + 127) / 128, 256>>>(feat, out, n);

    cudaStreamWaitEvent(0, g_ev_rb, 0);
    {
        dim3 grid(RSLOTS / 128, 27);
        tap_mma_kernel<<<grid, 256>>>(feat, out);
    }
    reduce_kernel<<<RED_BLOCKS, 256>>>(out, n);

    cudaStreamWaitEvent(0, g_ev_clear, 0);
    {
        const int n4 = n * (COUT / 4);
        bn_kernel<<<(n4 + 1023) / 1024, 256>>>(
            (float4*)out, gamma, beta, n4, 1.0f / (float)n);
    }
}